// round 11
// baseline (speedup 1.0000x reference)
#include <cuda_runtime.h>
#include <cuda_fp16.h>
#include <cstdint>

#define NN 50000
#define NPAD 50048          // 391 * 128
#define EE 1600000
#define RR 7
#define DD 128
#define GG 64
#define NS (NN*RR)
#define KK 1024             // R*D + D
#define NLAYERS 3
#define GSPLIT 16
#define MTILES (NPAD/128)   // 391
#define FUSED_SMEM 65536    // A tile 32KB + B tile 32KB (dynamic)

// ---------------- scratch (device globals; zero-initialized at load) -------
__device__ __align__(16) __half g_xh[2][(size_t)NN*DD];       // ping-pong x fp16
__device__ __align__(16) __half g_Bf3[NLAYERS][DD*KK];        // Wt fp16 [n][k]
__device__ __align__(16) float  g_bias3[NLAYERS][DD];
__device__ int   g_cnt[NS];
__device__ int   g_start[NS+1];
__device__ int   g_cur[NS];
__device__ __align__(8) int2 g_edge[EE];   // (src, ew bits)
__device__ int   g_bsum[512];

// ---------------- helpers ---------------------------------------------------
__device__ __forceinline__ uint32_t smem_u32(const void* p){
    uint32_t a;
    asm("{ .reg .u64 t; cvta.to.shared.u64 t, %1; cvt.u32.u64 %0, t; }" : "=r"(a) : "l"(p));
    return a;
}
#define SMEM_SWIZZLE_128B(o) ((o) ^ (((o) >> 3) & 0x70))

#define CP_ASYNC16(dst, src) \
    asm volatile("cp.async.cg.shared.global [%0], [%1], 16;" :: "r"(dst), "l"(src))
#define CP_COMMIT() asm volatile("cp.async.commit_group;" ::: "memory")
#define CP_WAIT0()  asm volatile("cp.async.wait_group 0;" ::: "memory")

__device__ __forceinline__ void ldsm4(uint32_t* r, uint32_t addr){
    asm volatile("ldmatrix.sync.aligned.m8n8.x4.shared.b16 {%0,%1,%2,%3}, [%4];"
        : "=r"(r[0]), "=r"(r[1]), "=r"(r[2]), "=r"(r[3]) : "r"(addr));
}
__device__ __forceinline__ void mma16816(float* c, const uint32_t* a, const uint32_t* b){
    asm volatile("mma.sync.aligned.m16n8k16.row.col.f32.f16.f16.f32 "
        "{%0,%1,%2,%3}, {%4,%5,%6,%7}, {%8,%9}, {%0,%1,%2,%3};"
        : "+f"(c[0]), "+f"(c[1]), "+f"(c[2]), "+f"(c[3])
        : "r"(a[0]), "r"(a[1]), "r"(a[2]), "r"(a[3]), "r"(b[0]), "r"(b[1]));
}

// ---------------- launch 0: embed (fp16 x buf 0) + zero g_cnt --------------
__global__ void k_embed_zero(const int* __restrict__ ut, const float4* __restrict__ emb4){
    int i = blockIdx.x*blockDim.x + threadIdx.x;
    if (i < NS) g_cnt[i] = 0;
    if (i < NN*32){
        int n = i >> 5, q = i & 31;
        float4 v = emb4[ut[n]*32 + q];
        *(__half2*)(g_xh[0] + (size_t)n*DD + q*4)     = __floats2half2_rn(v.x, v.y);
        *(__half2*)(g_xh[0] + (size_t)n*DD + q*4 + 2) = __floats2half2_rn(v.z, v.w);
    }
}
// launch 1
__global__ void k_hist(const int* __restrict__ nout, const int* __restrict__ rel){
    int e = blockIdx.x*blockDim.x + threadIdx.x;
    if (e < EE) atomicAdd(&g_cnt[nout[e]*RR + rel[e]], 1);
}
// launch 2
__global__ void k_scan1(){
    __shared__ int sm[1024];
    int t = threadIdx.x;
    int i = blockIdx.x*1024 + t;
    int v = (i < NS) ? g_cnt[i] : 0;
    sm[t] = v; __syncthreads();
    for (int off = 1; off < 1024; off <<= 1){
        int u = (t >= off) ? sm[t-off] : 0;
        __syncthreads();
        sm[t] += u;
        __syncthreads();
    }
    if (i < NS) g_start[i] = sm[t] - v;
    if (t == 1023) g_bsum[blockIdx.x] = sm[t];
}
// launch 3: fused scan2+scan3
__global__ void k_scan23(int nb){
    __shared__ int sm[512];
    int t = threadIdx.x;
    if (t < 512) sm[t] = (t < nb) ? g_bsum[t] : 0;
    __syncthreads();
    for (int off = 1; off < 512; off <<= 1){
        int u = 0;
        if (t < 512 && t >= off) u = sm[t-off];
        __syncthreads();
        if (t < 512) sm[t] += u;
        __syncthreads();
    }
    int boff = sm[blockIdx.x] - g_bsum[blockIdx.x];   // exclusive prefix of this block
    int i = blockIdx.x*1024 + t;
    if (i < NS){
        int s = g_start[i] + boff;
        g_start[i] = s;
        g_cur[i]   = s;
    }
    if (i == 0) g_start[NS] = EE;
}
// launch 4
__global__ void k_scatter(const int* __restrict__ nin, const int* __restrict__ nout,
                          const int* __restrict__ rel, const float* __restrict__ ewt){
    int e = blockIdx.x*blockDim.x + threadIdx.x;
    if (e < EE){
        int s = nout[e]*RR + rel[e];
        int p = atomicAdd(&g_cur[s], 1);
        g_edge[p] = make_int2(nin[e], __float_as_int(ewt[e]));
    }
}

// ---------------- weight transpose -> fp16, ALL layers ---------------------
__global__ void k_prepW(const float* __restrict__ Wrel, const float* __restrict__ brel,
                        const float* __restrict__ Wloop, const float* __restrict__ bloop){
    int i = blockIdx.x*blockDim.x + threadIdx.x;
    if (i < NLAYERS*KK*DD){
        int layer = i / (KK*DD);
        int rem   = i - layer*(KK*DD);
        int n = rem >> 10, k = rem & 1023;
        float v = (k < 896)
            ? Wrel [(size_t)layer*896*128 + (size_t)k*128 + n]
            : Wloop[(size_t)layer*128*128 + (size_t)(k-896)*128 + n];
        g_Bf3[layer][rem] = __float2half_rn(v);
    }
    if (i < NLAYERS*DD){
        int layer = i / DD, c = i - layer*DD;
        g_bias3[layer][c] = brel[layer*DD + c] + bloop[layer*DD + c];
    }
}

// ---------------- FUSED aggregate + GEMM per layer (ping-pong x) -----------
// Reads x from g_xh[pin], writes next-layer x to g_xh[pin^1] (no intra-launch
// read/write race). Each CTA: 128 node-rows; r=0..6 aggregates segment r into
// the swizzled smem A-tile then mmas it; r=7 cp.asyncs the x-aux columns.
__global__ void __launch_bounds__(256, 2) k_fused(float* __restrict__ xout,
                                                  int writeAux, int layer, int pin){
    extern __shared__ char dsm[];
    __shared__ int s_start[897];
    char* pA = dsm;                  // 32KB: 2 subtiles x 16KB (SW128, 64 cols each)
    uint32_t sA = smem_u32(pA);
    uint32_t sB = sA + 32768;        // 32KB: 2 subtiles x 16KB

    int tid  = threadIdx.x;
    int wid  = tid >> 5;
    int lane = tid & 31;
    int wm   = wid & 3;      // 4 warps along M (mma phase)
    int wn   = wid >> 2;     // 2 warps along N
    int m0   = blockIdx.x * 128;

    const __half* xin = g_xh[pin];
    __half*       xnx = g_xh[pin ^ 1];

    // cache this tile's CSR starts (128*7+1 entries), clamped to NS
    for (int i = tid; i < 897; i += 256){
        int idx = m0*7 + i; if (idx > NS) idx = NS;
        s_start[i] = __ldg(&g_start[idx]);
    }

    // B loader slots (4 x 16B per thread per 16KB subtile)
    int l_row[4], l_seg[4];
    #pragma unroll
    for (int i = 0; i < 4; i++){
        int idx = tid + i*256;
        l_row[i] = idx >> 3;
        l_seg[i] = (idx & 7) * 16;
    }
    const char* Bsrc = (const char*)g_Bf3[layer];

    // ldsm addressing (un-swizzled components; swizzle applied per ks)
    uint32_t a_rowb = (uint32_t)(((lane & 7) + ((lane >> 3) & 1) * 8 + wm * 32) * 128);
    uint32_t a_kb   = ((lane >> 4) & 1) * 16;
    uint32_t b_rowb = (uint32_t)(((lane & 7) + ((lane >> 4) & 1) * 8 + wn * 64) * 128);
    uint32_t b_kb   = ((lane >> 3) & 1) * 16;

    float acc[2][8][4];
    #pragma unroll
    for (int mt = 0; mt < 2; mt++)
        #pragma unroll
        for (int nt = 0; nt < 8; nt++)
            #pragma unroll
            for (int q = 0; q < 4; q++) acc[mt][nt][q] = 0.f;

    const uint2* xh = (const uint2*)xin;     // 8B = 4 halves; 32 lanes = 128 cols
    int nbase = wid * 16;                    // aggregation: warp handles 16 rows
    uint32_t sts_sub = (uint32_t)(lane >> 4) * 16384;

    __syncthreads();   // s_start visible

    for (int r = 0; r < 8; r++){
        // issue B chunks (global chunk kc = r*2+sub; byte col offset = kc*128)
        #pragma unroll
        for (int sub = 0; sub < 2; sub++){
            #pragma unroll
            for (int i = 0; i < 4; i++){
                const char* src = Bsrc + (size_t)l_row[i]*2048 + (r*2+sub)*128 + l_seg[i];
                CP_ASYNC16(sB + sub*16384 + SMEM_SWIZZLE_128B(l_row[i]*128 + l_seg[i]), src);
            }
        }
        if (r == 7){
            // x-aux: copy 128 rows x 256B of xin into the A stage
            #pragma unroll
            for (int i = 0; i < 8; i++){
                int idx = tid + i*256;      // 0..2047
                int row = idx >> 4;
                int seg = idx & 15;         // 16B segment within 256B row
                int gr = m0 + row; if (gr >= NN) gr = NN - 1;   // clamp (rows>=NN unused)
                const char* src = (const char*)xin + (size_t)gr*256 + seg*16;
                CP_ASYNC16(sA + (seg>>3)*16384 + SMEM_SWIZZLE_128B(row*128 + (seg&7)*16), src);
            }
        }
        CP_COMMIT();

        if (r < 7){
            // aggregate segment r for this warp's 16 rows into smem A-tile
            for (int ni = 0; ni < 16; ni++){
                int row = nbase + ni;
                int beg = s_start[row*7 + r], end = s_start[row*7 + r + 1];
                float4 a = make_float4(0.f, 0.f, 0.f, 0.f);
                int j = beg;
                for (; j + 1 < end; j += 2){
                    int2 e0 = __ldg(&g_edge[j]);
                    int2 e1 = __ldg(&g_edge[j+1]);
                    uint2 r0 = __ldg(&xh[(size_t)e0.x*32 + lane]);
                    uint2 r1 = __ldg(&xh[(size_t)e1.x*32 + lane]);
                    float w0 = __int_as_float(e0.y), w1 = __int_as_float(e1.y);
                    float2 a0 = __half22float2(*(__half2*)&r0.x), b0 = __half22float2(*(__half2*)&r0.y);
                    float2 a1 = __half22float2(*(__half2*)&r1.x), b1 = __half22float2(*(__half2*)&r1.y);
                    a.x += w0*a0.x + w1*a1.x;
                    a.y += w0*a0.y + w1*a1.y;
                    a.z += w0*b0.x + w1*b1.x;
                    a.w += w0*b0.y + w1*b1.y;
                }
                if (j < end){
                    int2 e0 = __ldg(&g_edge[j]);
                    float w0 = __int_as_float(e0.y);
                    uint2 r0 = __ldg(&xh[(size_t)e0.x*32 + lane]);
                    float2 a0 = __half22float2(*(__half2*)&r0.x);
                    float2 b0 = __half22float2(*(__half2*)&r0.y);
                    a.x += w0*a0.x; a.y += w0*a0.y; a.z += w0*b0.x; a.w += w0*b0.y;
                }
                __half2 h01 = __floats2half2_rn(a.x, a.y);
                __half2 h23 = __floats2half2_rn(a.z, a.w);
                uint2 u; u.x = *(uint32_t*)&h01; u.y = *(uint32_t*)&h23;
                uint32_t off = SMEM_SWIZZLE_128B((uint32_t)(row*128 + (lane & 15)*8));
                *(uint2*)(pA + sts_sub + off) = u;
            }
        }

        CP_WAIT0();
        __syncthreads();

        // mma on the 2 subchunks of this r
        #pragma unroll
        for (int sub = 0; sub < 2; sub++){
            uint32_t tA = sA + sub*16384;
            uint32_t tB = sB + sub*16384;
            #pragma unroll
            for (int ks = 0; ks < 4; ks++){
                uint32_t koff = ks * 32;
                uint32_t a_off = SMEM_SWIZZLE_128B(a_rowb + a_kb + koff);
                uint32_t b_off = SMEM_SWIZZLE_128B(b_rowb + b_kb + koff);
                uint32_t af[2][4];
                #pragma unroll
                for (int mt = 0; mt < 2; mt++)
                    ldsm4(af[mt], tA + a_off + mt*2048);
                #pragma unroll
                for (int np = 0; np < 4; np++){
                    uint32_t bf[4];
                    ldsm4(bf, tB + b_off + np*2048);
                    #pragma unroll
                    for (int half = 0; half < 2; half++){
                        int nt = np*2 + half;
                        #pragma unroll
                        for (int mt = 0; mt < 2; mt++)
                            mma16816(acc[mt][nt], af[mt], bf + half*2);
                    }
                }
            }
        }
        __syncthreads();
    }

    // epilogue: bias + relu
    const float* bias = g_bias3[layer];
    int qrow = lane >> 2;            // 0..7
    int qcol = (lane & 3) * 2;       // 0,2,4,6
    #pragma unroll
    for (int mt = 0; mt < 2; mt++){
        #pragma unroll
        for (int nt = 0; nt < 8; nt++){
            int col  = wn*64 + nt*8 + qcol;
            float2 bb = *(const float2*)&bias[col];
            int r0 = m0 + wm*32 + mt*16 + qrow;
            int r1 = r0 + 8;
            float v00 = fmaxf(acc[mt][nt][0] + bb.x, 0.f);
            float v01 = fmaxf(acc[mt][nt][1] + bb.y, 0.f);
            float v10 = fmaxf(acc[mt][nt][2] + bb.x, 0.f);
            float v11 = fmaxf(acc[mt][nt][3] + bb.y, 0.f);
            if (writeAux){
                if (r0 < NN) *(__half2*)&xnx[(size_t)r0*DD + col] = __floats2half2_rn(v00, v01);
                if (r1 < NN) *(__half2*)&xnx[(size_t)r1*DD + col] = __floats2half2_rn(v10, v11);
            } else {
                if (r0 < NN) *(float2*)&xout[(size_t)r0*DD + col] = make_float2(v00, v01);
                if (r1 < NN) *(float2*)&xout[(size_t)r1*DD + col] = make_float2(v10, v11);
            }
        }
    }
}

// ---------------- graph pooling --------------------------------------------
__global__ void k_zero_out(float* __restrict__ out){
    int i = blockIdx.x*blockDim.x + threadIdx.x;
    if (i < GG*DD) out[i] = 0.f;
}
__device__ __forceinline__ int lowerb(const int* __restrict__ a, int n, int key){
    int lo = 0, hi = n;
    while (lo < hi){
        int mid = (lo + hi) >> 1;
        if (a[mid] < key) lo = mid + 1; else hi = mid;
    }
    return lo;
}
__global__ void k_gsum(const int* __restrict__ n2g, const float* __restrict__ x,
                       float* __restrict__ out){
    int g = blockIdx.x / GSPLIT, c = blockIdx.x % GSPLIT, t = threadIdx.x;
    int lo = lowerb(n2g, NN, g);
    int hi = lowerb(n2g, NN, g+1);
    int len = hi - lo;
    int per = (len + GSPLIT - 1) / GSPLIT;
    int s = lo + c*per;
    int e = min(s + per, hi);
    float acc = 0.f;
    for (int n = s; n < e; n++) acc += x[(size_t)n*DD + t];
    if (e > s) atomicAdd(&out[g*DD + t], acc);
}

// ---------------- launcher --------------------------------------------------
extern "C" void kernel_launch(void* const* d_in, const int* in_sizes, int n_in,
                              void* d_out, int out_size){
    const int*   unit_type   = (const int*)  d_in[0];
    const int*   node_in     = (const int*)  d_in[1];
    const int*   node_out    = (const int*)  d_in[2];
    const int*   relation    = (const int*)  d_in[3];
    const float* edge_weight = (const float*)d_in[4];
    const int*   node2graph  = (const int*)  d_in[5];
    const float* emb         = (const float*)d_in[6];
    const float* W_rel       = (const float*)d_in[7];
    const float* b_rel       = (const float*)d_in[8];
    const float* W_loop      = (const float*)d_in[9];
    const float* b_loop      = (const float*)d_in[10];

    float* out   = (float*)d_out;
    float* x_out = out + GG*DD;

    // idempotent, capture-safe; no static guard (harness rule)
    cudaFuncSetAttribute(k_fused, cudaFuncAttributeMaxDynamicSharedMemorySize, FUSED_SMEM);

    int nb_ns = (NS + 1023) / 1024;  // 342

    k_embed_zero<<<(NN*32 + 255)/256, 256>>>(unit_type, (const float4*)emb);
    k_hist<<<(EE + 255)/256, 256>>>(node_out, relation);
    k_scan1<<<nb_ns, 1024>>>();
    k_scan23<<<nb_ns, 1024>>>(nb_ns);
    k_scatter<<<(EE + 255)/256, 256>>>(node_in, node_out, relation, edge_weight);
    k_prepW<<<(NLAYERS*KK*DD + 255)/256, 256>>>(W_rel, b_rel, W_loop, b_loop);

    for (int l = 0; l < NLAYERS; l++){
        int pin = l & 1;
        if (l < NLAYERS - 1)
            k_fused<<<MTILES, 256, FUSED_SMEM>>>(nullptr, 1, l, pin);
        else
            k_fused<<<MTILES, 256, FUSED_SMEM>>>(x_out, 0, l, pin);
    }

    k_zero_out<<<(GG*DD + 255)/256, 256>>>(out);
    k_gsum<<<GG*GSPLIT, 128>>>(node2graph, x_out, out);
}

// round 12
// speedup vs baseline: 3.3163x; 3.3163x over previous
#include <cuda_runtime.h>
#include <cuda_fp16.h>
#include <cstdint>

#define NN 50000
#define NPAD 50048          // 391 * 128
#define EE 1600000
#define RR 7
#define DD 128
#define GG 64
#define NS (NN*RR)
#define KK 1024             // R*D + D
#define NLAYERS 3
#define GSPLIT 16
#define NCHUNK 16           // K chunks of 64
#define MTILES (NPAD/128)   // 391
#define STAGE_BYTES 32768   // 2 tiles x 16KB
#define GEMM_SMEM (2*STAGE_BYTES)

// ---------------- scratch (device globals; zero-initialized at load) -------
__device__ __align__(16) __half g_Af[(size_t)NPAD*KK];        // A in fp16 (102MB)
__device__ __align__(16) __half g_xh[(size_t)NN*DD];          // x in fp16 (12.8MB)
__device__ __align__(16) __half g_Bf3[NLAYERS][DD*KK];        // Wt fp16 [n][k]
__device__ __align__(16) float  g_bias3[NLAYERS][DD];
__device__ int   g_cnt[NS];
__device__ int   g_start[NS+1];
__device__ int   g_cur[NS];
__device__ __align__(8) int2 g_edge[EE];   // (src, ew bits)
__device__ int   g_bsum[512];

// ---------------- helpers ---------------------------------------------------
__device__ __forceinline__ uint32_t smem_u32(const void* p){
    uint32_t a;
    asm("{ .reg .u64 t; cvta.to.shared.u64 t, %1; cvt.u32.u64 %0, t; }" : "=r"(a) : "l"(p));
    return a;
}
#define SMEM_SWIZZLE_128B(o) ((o) ^ (((o) >> 3) & 0x70))

#define CP_ASYNC16(dst, src) \
    asm volatile("cp.async.cg.shared.global [%0], [%1], 16;" :: "r"(dst), "l"(src))
#define CP_COMMIT() asm volatile("cp.async.commit_group;" ::: "memory")
#define CP_WAIT1()  asm volatile("cp.async.wait_group 1;" ::: "memory")
#define CP_WAIT0()  asm volatile("cp.async.wait_group 0;" ::: "memory")

__device__ __forceinline__ void ldsm4(uint32_t* r, uint32_t addr){
    asm volatile("ldmatrix.sync.aligned.m8n8.x4.shared.b16 {%0,%1,%2,%3}, [%4];"
        : "=r"(r[0]), "=r"(r[1]), "=r"(r[2]), "=r"(r[3]) : "r"(addr));
}
__device__ __forceinline__ void mma16816(float* c, const uint32_t* a, const uint32_t* b){
    asm volatile("mma.sync.aligned.m16n8k16.row.col.f32.f16.f16.f32 "
        "{%0,%1,%2,%3}, {%4,%5,%6,%7}, {%8,%9}, {%0,%1,%2,%3};"
        : "+f"(c[0]), "+f"(c[1]), "+f"(c[2]), "+f"(c[3])
        : "r"(a[0]), "r"(a[1]), "r"(a[2]), "r"(a[3]), "r"(b[0]), "r"(b[1]));
}

__device__ __forceinline__ void h_store4(size_t off, float4 v){
    *(__half2*)(g_Af + off)     = __floats2half2_rn(v.x, v.y);
    *(__half2*)(g_Af + off + 2) = __floats2half2_rn(v.z, v.w);
}

// ---------------- launch 0: embed (fp16 x + A aux cols) + zero g_cnt -------
__global__ void k_embed_zero(const int* __restrict__ ut, const float4* __restrict__ emb4){
    int i = blockIdx.x*blockDim.x + threadIdx.x;
    if (i < NS) g_cnt[i] = 0;
    if (i < NN*32){
        int n = i >> 5, q = i & 31;
        float4 v = emb4[ut[n]*32 + q];
        __half2 h01 = __floats2half2_rn(v.x, v.y);
        __half2 h23 = __floats2half2_rn(v.z, v.w);
        *(__half2*)(g_xh + (size_t)n*DD + q*4)     = h01;
        *(__half2*)(g_xh + (size_t)n*DD + q*4 + 2) = h23;
        *(__half2*)(g_Af + (size_t)n*KK + 896 + q*4)     = h01;
        *(__half2*)(g_Af + (size_t)n*KK + 896 + q*4 + 2) = h23;
    }
}
// launch 1
__global__ void k_hist(const int* __restrict__ nout, const int* __restrict__ rel){
    int e = blockIdx.x*blockDim.x + threadIdx.x;
    if (e < EE) atomicAdd(&g_cnt[nout[e]*RR + rel[e]], 1);
}
// launch 2
__global__ void k_scan1(){
    __shared__ int sm[1024];
    int t = threadIdx.x;
    int i = blockIdx.x*1024 + t;
    int v = (i < NS) ? g_cnt[i] : 0;
    sm[t] = v; __syncthreads();
    for (int off = 1; off < 1024; off <<= 1){
        int u = (t >= off) ? sm[t-off] : 0;
        __syncthreads();
        sm[t] += u;
        __syncthreads();
    }
    if (i < NS) g_start[i] = sm[t] - v;
    if (t == 1023) g_bsum[blockIdx.x] = sm[t];
}
// launch 3: fused scan2+scan3
__global__ void k_scan23(int nb){
    __shared__ int sm[512];
    int t = threadIdx.x;
    if (t < 512) sm[t] = (t < nb) ? g_bsum[t] : 0;
    __syncthreads();
    for (int off = 1; off < 512; off <<= 1){
        int u = 0;
        if (t < 512 && t >= off) u = sm[t-off];
        __syncthreads();
        if (t < 512) sm[t] += u;
        __syncthreads();
    }
    int boff = sm[blockIdx.x] - g_bsum[blockIdx.x];   // exclusive prefix of this block
    int i = blockIdx.x*1024 + t;
    if (i < NS){
        int s = g_start[i] + boff;
        g_start[i] = s;
        g_cur[i]   = s;
    }
    if (i == 0) g_start[NS] = EE;
}
// launch 4: scatter + zero the graph-pool output (independent work fused in)
__global__ void k_scatter(const int* __restrict__ nin, const int* __restrict__ nout,
                          const int* __restrict__ rel, const float* __restrict__ ewt,
                          float* __restrict__ out){
    int e = blockIdx.x*blockDim.x + threadIdx.x;
    if (e < GG*DD) out[e] = 0.f;
    if (e < EE){
        int s = nout[e]*RR + rel[e];
        int p = atomicAdd(&g_cur[s], 1);
        g_edge[p] = make_int2(nin[e], __float_as_int(ewt[e]));
    }
}

// ---------------- per-layer aggregate: warp/segment, fp16 gather, unroll-4 -
// Block = 8 contiguous segments; starts cached in smem (coalesced, kills the
// per-warp dependent start-load prefix).
__global__ void k_agg(){
    __shared__ int s_st[9];
    int wseg0 = blockIdx.x * 8;
    if (threadIdx.x < 9){
        int idx = wseg0 + threadIdx.x;
        s_st[threadIdx.x] = __ldg(&g_start[idx]);   // idx <= NS always (8 | NS)
    }
    __syncthreads();
    int wl = threadIdx.x >> 5;
    int w  = wseg0 + wl;
    if (w >= NS) return;
    int lane = threadIdx.x & 31;
    int beg = s_st[wl], end = s_st[wl + 1];
    const uint2* xh = (const uint2*)g_xh;   // 8B = 4 halves per lane; 32 lanes = 128 cols
    float4 acc = make_float4(0.f, 0.f, 0.f, 0.f);
    int j = beg;
    for (; j + 3 < end; j += 4){
        int2 e0 = __ldg(&g_edge[j]);
        int2 e1 = __ldg(&g_edge[j+1]);
        int2 e2 = __ldg(&g_edge[j+2]);
        int2 e3 = __ldg(&g_edge[j+3]);
        uint2 r0 = __ldg(&xh[(size_t)e0.x*32 + lane]);
        uint2 r1 = __ldg(&xh[(size_t)e1.x*32 + lane]);
        uint2 r2 = __ldg(&xh[(size_t)e2.x*32 + lane]);
        uint2 r3 = __ldg(&xh[(size_t)e3.x*32 + lane]);
        float w0 = __int_as_float(e0.y), w1 = __int_as_float(e1.y);
        float w2 = __int_as_float(e2.y), w3 = __int_as_float(e3.y);
        float2 a0 = __half22float2(*(__half2*)&r0.x), b0 = __half22float2(*(__half2*)&r0.y);
        float2 a1 = __half22float2(*(__half2*)&r1.x), b1 = __half22float2(*(__half2*)&r1.y);
        float2 a2 = __half22float2(*(__half2*)&r2.x), b2 = __half22float2(*(__half2*)&r2.y);
        float2 a3 = __half22float2(*(__half2*)&r3.x), b3 = __half22float2(*(__half2*)&r3.y);
        acc.x += w0*a0.x + w1*a1.x + w2*a2.x + w3*a3.x;
        acc.y += w0*a0.y + w1*a1.y + w2*a2.y + w3*a3.y;
        acc.z += w0*b0.x + w1*b1.x + w2*b2.x + w3*b3.x;
        acc.w += w0*b0.y + w1*b1.y + w2*b2.y + w3*b3.y;
    }
    for (; j < end; j++){
        int2 e0 = __ldg(&g_edge[j]);
        float w0 = __int_as_float(e0.y);
        uint2 r0 = __ldg(&xh[(size_t)e0.x*32 + lane]);
        float2 a0 = __half22float2(*(__half2*)&r0.x);
        float2 b0 = __half22float2(*(__half2*)&r0.y);
        acc.x += w0*a0.x; acc.y += w0*a0.y; acc.z += w0*b0.x; acc.w += w0*b0.y;
    }
    int n = w / RR, r = w - n*RR;
    h_store4((size_t)n*KK + r*DD + lane*4, acc);
}

// ---------------- weight transpose -> fp16, ALL layers ---------------------
__global__ void k_prepW(const float* __restrict__ Wrel, const float* __restrict__ brel,
                        const float* __restrict__ Wloop, const float* __restrict__ bloop){
    int i = blockIdx.x*blockDim.x + threadIdx.x;
    if (i < NLAYERS*KK*DD){
        int layer = i / (KK*DD);
        int rem   = i - layer*(KK*DD);
        int n = rem >> 10, k = rem & 1023;
        float v = (k < 896)
            ? Wrel [(size_t)layer*896*128 + (size_t)k*128 + n]
            : Wloop[(size_t)layer*128*128 + (size_t)(k-896)*128 + n];
        g_Bf3[layer][rem] = __float2half_rn(v);
    }
    if (i < NLAYERS*DD){
        int layer = i / DD, c = i - layer*DD;
        g_bias3[layer][c] = brel[layer*DD + c] + bloop[layer*DD + c];
    }
}

// ---------------- pipelined mma.sync GEMM (plain fp16) ---------------------
// C[128tile,128] = Af * Bf^T, fp32 accum. Stage = 2 tiles x 16KB. 2 CTAs/SM.
__global__ void __launch_bounds__(256, 2) k_gemm_mma(float* __restrict__ xout,
                                                     int writeAux, int layer){
    extern __shared__ char dsm[];
    uint32_t sbase = smem_u32(dsm);

    int tid  = threadIdx.x;
    int wid  = tid >> 5;
    int lane = tid & 31;
    int wm   = wid & 3;      // 4 warps along M
    int wn   = wid >> 2;     // 2 warps along N
    int m0   = blockIdx.x * 128;

    const char* srcs[2] = {
        (const char*)g_Af + (size_t)m0*2048,
        (const char*)g_Bf3[layer] };

    int l_row[4], l_seg[4];
    #pragma unroll
    for (int i = 0; i < 4; i++){
        int idx = tid + i*256;
        l_row[i] = idx >> 3;
        l_seg[i] = (idx & 7) * 16;
    }

    uint32_t a_rowb = (uint32_t)(((lane & 7) + ((lane >> 3) & 1) * 8 + wm * 32) * 128);
    uint32_t a_kb   = ((lane >> 4) & 1) * 16;
    uint32_t b_rowb = (uint32_t)(((lane & 7) + ((lane >> 4) & 1) * 8 + wn * 64) * 128);
    uint32_t b_kb   = ((lane >> 3) & 1) * 16;

    float acc[2][8][4];
    #pragma unroll
    for (int mt = 0; mt < 2; mt++)
        #pragma unroll
        for (int nt = 0; nt < 8; nt++)
            #pragma unroll
            for (int q = 0; q < 4; q++) acc[mt][nt][q] = 0.f;

    auto issue = [&](int kc, int stage){
        size_t kbyte = (size_t)kc * 128;
        uint32_t sb = sbase + stage*STAGE_BYTES;
        #pragma unroll
        for (int t2 = 0; t2 < 2; t2++){
            #pragma unroll
            for (int i = 0; i < 4; i++){
                const char* src = srcs[t2] + (size_t)l_row[i]*2048 + kbyte + l_seg[i];
                uint32_t dst = sb + t2*16384 + SMEM_SWIZZLE_128B(l_row[i]*128 + l_seg[i]);
                CP_ASYNC16(dst, src);
            }
        }
    };

    issue(0, 0);
    CP_COMMIT();

    for (int kc = 0; kc < NCHUNK; kc++){
        if (kc + 1 < NCHUNK){
            issue(kc + 1, (kc + 1) & 1);
            CP_COMMIT();
            CP_WAIT1();
        } else {
            CP_WAIT0();
        }
        __syncthreads();

        uint32_t sb  = sbase + (kc & 1)*STAGE_BYTES;
        uint32_t sAF = sb, sBF = sb + 16384;

        #pragma unroll
        for (int ks = 0; ks < 4; ks++){
            uint32_t koff = ks * 32;
            uint32_t a_off = SMEM_SWIZZLE_128B(a_rowb + a_kb + koff);
            uint32_t b_off = SMEM_SWIZZLE_128B(b_rowb + b_kb + koff);
            uint32_t af[2][4];
            #pragma unroll
            for (int mt = 0; mt < 2; mt++)
                ldsm4(af[mt], sAF + a_off + mt*2048);
            #pragma unroll
            for (int np = 0; np < 4; np++){
                uint32_t bf[4];
                ldsm4(bf, sBF + b_off + np*2048);
                #pragma unroll
                for (int half = 0; half < 2; half++){
                    int nt = np*2 + half;
                    #pragma unroll
                    for (int mt = 0; mt < 2; mt++)
                        mma16816(acc[mt][nt], af[mt], bf + half*2);
                }
            }
        }
        __syncthreads();
    }

    // epilogue: bias + relu
    const float* bias = g_bias3[layer];
    int qrow = lane >> 2;            // 0..7
    int qcol = (lane & 3) * 2;       // 0,2,4,6
    #pragma unroll
    for (int mt = 0; mt < 2; mt++){
        #pragma unroll
        for (int nt = 0; nt < 8; nt++){
            int col  = wn*64 + nt*8 + qcol;
            float2 bb = *(const float2*)&bias[col];
            int r0 = m0 + wm*32 + mt*16 + qrow;
            int r1 = r0 + 8;
            float v00 = fmaxf(acc[mt][nt][0] + bb.x, 0.f);
            float v01 = fmaxf(acc[mt][nt][1] + bb.y, 0.f);
            float v10 = fmaxf(acc[mt][nt][2] + bb.x, 0.f);
            float v11 = fmaxf(acc[mt][nt][3] + bb.y, 0.f);
            if (writeAux){
                if (r0 < NN){
                    __half2 h = __floats2half2_rn(v00, v01);
                    *(__half2*)&g_xh[(size_t)r0*DD + col] = h;
                    *(__half2*)&g_Af[(size_t)r0*KK + 896 + col] = h;
                }
                if (r1 < NN){
                    __half2 h = __floats2half2_rn(v10, v11);
                    *(__half2*)&g_xh[(size_t)r1*DD + col] = h;
                    *(__half2*)&g_Af[(size_t)r1*KK + 896 + col] = h;
                }
            } else {
                if (r0 < NN) *(float2*)&xout[(size_t)r0*DD + col] = make_float2(v00, v01);
                if (r1 < NN) *(float2*)&xout[(size_t)r1*DD + col] = make_float2(v10, v11);
            }
        }
    }
}

// ---------------- graph pooling --------------------------------------------
__device__ __forceinline__ int lowerb(const int* __restrict__ a, int n, int key){
    int lo = 0, hi = n;
    while (lo < hi){
        int mid = (lo + hi) >> 1;
        if (a[mid] < key) lo = mid + 1; else hi = mid;
    }
    return lo;
}
__global__ void k_gsum(const int* __restrict__ n2g, const float* __restrict__ x,
                       float* __restrict__ out){
    int g = blockIdx.x / GSPLIT, c = blockIdx.x % GSPLIT, t = threadIdx.x;
    int lo = lowerb(n2g, NN, g);
    int hi = lowerb(n2g, NN, g+1);
    int len = hi - lo;
    int per = (len + GSPLIT - 1) / GSPLIT;
    int s = lo + c*per;
    int e = min(s + per, hi);
    float acc = 0.f;
    for (int n = s; n < e; n++) acc += x[(size_t)n*DD + t];
    if (e > s) atomicAdd(&out[g*DD + t], acc);
}

// ---------------- launcher --------------------------------------------------
extern "C" void kernel_launch(void* const* d_in, const int* in_sizes, int n_in,
                              void* d_out, int out_size){
    const int*   unit_type   = (const int*)  d_in[0];
    const int*   node_in     = (const int*)  d_in[1];
    const int*   node_out    = (const int*)  d_in[2];
    const int*   relation    = (const int*)  d_in[3];
    const float* edge_weight = (const float*)d_in[4];
    const int*   node2graph  = (const int*)  d_in[5];
    const float* emb         = (const float*)d_in[6];
    const float* W_rel       = (const float*)d_in[7];
    const float* b_rel       = (const float*)d_in[8];
    const float* W_loop      = (const float*)d_in[9];
    const float* b_loop      = (const float*)d_in[10];

    float* out   = (float*)d_out;
    float* x_out = out + GG*DD;

    // idempotent, capture-safe; no static guard (harness rule)
    cudaFuncSetAttribute(k_gemm_mma, cudaFuncAttributeMaxDynamicSharedMemorySize, GEMM_SMEM);

    int nb_ns = (NS + 1023) / 1024;  // 342

    k_embed_zero<<<(NN*32 + 255)/256, 256>>>(unit_type, (const float4*)emb);
    k_hist<<<(EE + 255)/256, 256>>>(node_out, relation);
    k_scan1<<<nb_ns, 1024>>>();
    k_scan23<<<nb_ns, 1024>>>(nb_ns);
    k_scatter<<<(EE + 255)/256, 256>>>(node_in, node_out, relation, edge_weight, out);

    for (int l = 0; l < NLAYERS; l++){
        k_agg<<<NS/8, 256>>>();
        if (l == 0)
            k_prepW<<<(NLAYERS*KK*DD + 255)/256, 256>>>(W_rel, b_rel, W_loop, b_loop);
        if (l < NLAYERS - 1)
            k_gemm_mma<<<MTILES, 256, GEMM_SMEM>>>(nullptr, 1, l);
        else
            k_gemm_mma<<<MTILES, 256, GEMM_SMEM>>>(x_out, 0, l);
    }

    k_gsum<<<GG*GSPLIT, 128>>>(node2graph, x_out, out);
}

// round 13
// speedup vs baseline: 3.4330x; 1.0352x over previous
#include <cuda_runtime.h>
#include <cuda_fp16.h>
#include <cstdint>

#define NN 50000
#define NPAD 50048          // 391 * 128
#define EE 1600000
#define RR 7
#define DD 128
#define GG 64
#define NS (NN*RR)
#define KK 1024             // R*D + D
#define NLAYERS 3
#define GSPLIT 16
#define NCHUNK 16           // K chunks of 64
#define MTILES (NPAD/128)   // 391
#define STAGE_BYTES 32768   // A tile 16KB + B tile 16KB
#define NSTAGE 3
#define GEMM_SMEM (NSTAGE*STAGE_BYTES)   // 96KB

// ---------------- scratch (device globals; zero-initialized at load) -------
__device__ __align__(16) __half g_Af[(size_t)NPAD*KK];        // A in fp16 (102MB)
__device__ __align__(16) __half g_xh[(size_t)NN*DD];          // x in fp16 (12.8MB)
__device__ __align__(16) __half g_Bf3[NLAYERS][DD*KK];        // Wt fp16 [n][k]
__device__ __align__(16) float  g_bias3[NLAYERS][DD];
__device__ int   g_cnt[NS];
__device__ int   g_start[NS+1];
__device__ int   g_cur[NS];
__device__ __align__(8) int2 g_edge[EE];   // (src, ew bits)
__device__ int   g_bsum[512];

// ---------------- helpers ---------------------------------------------------
__device__ __forceinline__ uint32_t smem_u32(const void* p){
    uint32_t a;
    asm("{ .reg .u64 t; cvta.to.shared.u64 t, %1; cvt.u32.u64 %0, t; }" : "=r"(a) : "l"(p));
    return a;
}
#define SMEM_SWIZZLE_128B(o) ((o) ^ (((o) >> 3) & 0x70))

#define CP_ASYNC16(dst, src) \
    asm volatile("cp.async.cg.shared.global [%0], [%1], 16;" :: "r"(dst), "l"(src))
#define CP_COMMIT() asm volatile("cp.async.commit_group;" ::: "memory")
#define CP_WAIT1()  asm volatile("cp.async.wait_group 1;" ::: "memory")
#define CP_WAIT0()  asm volatile("cp.async.wait_group 0;" ::: "memory")

__device__ __forceinline__ void ldsm4(uint32_t* r, uint32_t addr){
    asm volatile("ldmatrix.sync.aligned.m8n8.x4.shared.b16 {%0,%1,%2,%3}, [%4];"
        : "=r"(r[0]), "=r"(r[1]), "=r"(r[2]), "=r"(r[3]) : "r"(addr));
}
__device__ __forceinline__ void mma16816(float* c, const uint32_t* a, const uint32_t* b){
    asm volatile("mma.sync.aligned.m16n8k16.row.col.f32.f16.f16.f32 "
        "{%0,%1,%2,%3}, {%4,%5,%6,%7}, {%8,%9}, {%0,%1,%2,%3};"
        : "+f"(c[0]), "+f"(c[1]), "+f"(c[2]), "+f"(c[3])
        : "r"(a[0]), "r"(a[1]), "r"(a[2]), "r"(a[3]), "r"(b[0]), "r"(b[1]));
}

__device__ __forceinline__ void h_store4(size_t off, float4 v){
    *(__half2*)(g_Af + off)     = __floats2half2_rn(v.x, v.y);
    *(__half2*)(g_Af + off + 2) = __floats2half2_rn(v.z, v.w);
}

// ---------------- launch 0: embed (fp16 x + A aux cols) + zero g_cnt -------
__global__ void k_embed_zero(const int* __restrict__ ut, const float4* __restrict__ emb4){
    int i = blockIdx.x*blockDim.x + threadIdx.x;
    if (i < NS) g_cnt[i] = 0;
    if (i < NN*32){
        int n = i >> 5, q = i & 31;
        float4 v = emb4[ut[n]*32 + q];
        __half2 h01 = __floats2half2_rn(v.x, v.y);
        __half2 h23 = __floats2half2_rn(v.z, v.w);
        *(__half2*)(g_xh + (size_t)n*DD + q*4)     = h01;
        *(__half2*)(g_xh + (size_t)n*DD + q*4 + 2) = h23;
        *(__half2*)(g_Af + (size_t)n*KK + 896 + q*4)     = h01;
        *(__half2*)(g_Af + (size_t)n*KK + 896 + q*4 + 2) = h23;
    }
}
// launch 1
__global__ void k_hist(const int* __restrict__ nout, const int* __restrict__ rel){
    int e = blockIdx.x*blockDim.x + threadIdx.x;
    if (e < EE) atomicAdd(&g_cnt[nout[e]*RR + rel[e]], 1);
}
// launch 2
__global__ void k_scan1(){
    __shared__ int sm[1024];
    int t = threadIdx.x;
    int i = blockIdx.x*1024 + t;
    int v = (i < NS) ? g_cnt[i] : 0;
    sm[t] = v; __syncthreads();
    for (int off = 1; off < 1024; off <<= 1){
        int u = (t >= off) ? sm[t-off] : 0;
        __syncthreads();
        sm[t] += u;
        __syncthreads();
    }
    if (i < NS) g_start[i] = sm[t] - v;
    if (t == 1023) g_bsum[blockIdx.x] = sm[t];
}
// launch 3: fused scan2+scan3
__global__ void k_scan23(int nb){
    __shared__ int sm[512];
    int t = threadIdx.x;
    if (t < 512) sm[t] = (t < nb) ? g_bsum[t] : 0;
    __syncthreads();
    for (int off = 1; off < 512; off <<= 1){
        int u = 0;
        if (t < 512 && t >= off) u = sm[t-off];
        __syncthreads();
        if (t < 512) sm[t] += u;
        __syncthreads();
    }
    int boff = sm[blockIdx.x] - g_bsum[blockIdx.x];   // exclusive prefix of this block
    int i = blockIdx.x*1024 + t;
    if (i < NS){
        int s = g_start[i] + boff;
        g_start[i] = s;
        g_cur[i]   = s;
    }
    if (i == 0) g_start[NS] = EE;
}
// launch 4: scatter + zero the graph-pool output (independent work fused in)
__global__ void k_scatter(const int* __restrict__ nin, const int* __restrict__ nout,
                          const int* __restrict__ rel, const float* __restrict__ ewt,
                          float* __restrict__ out){
    int e = blockIdx.x*blockDim.x + threadIdx.x;
    if (e < GG*DD) out[e] = 0.f;
    if (e < EE){
        int s = nout[e]*RR + rel[e];
        int p = atomicAdd(&g_cur[s], 1);
        g_edge[p] = make_int2(nin[e], __float_as_int(ewt[e]));
    }
}

// ---------------- per-layer aggregate: warp/segment, fp16 gather, unroll-4 -
// (exact R9 form — per-warp start loads; no block-level serialization)
__global__ void k_agg(){
    int w = (blockIdx.x*blockDim.x + threadIdx.x) >> 5;
    int lane = threadIdx.x & 31;
    if (w >= NS) return;
    int beg = __ldg(&g_start[w]), end = __ldg(&g_start[w+1]);
    const uint2* xh = (const uint2*)g_xh;   // 8B = 4 halves per lane; 32 lanes = 128 cols
    float4 acc = make_float4(0.f, 0.f, 0.f, 0.f);
    int j = beg;
    for (; j + 3 < end; j += 4){
        int2 e0 = __ldg(&g_edge[j]);
        int2 e1 = __ldg(&g_edge[j+1]);
        int2 e2 = __ldg(&g_edge[j+2]);
        int2 e3 = __ldg(&g_edge[j+3]);
        uint2 r0 = __ldg(&xh[(size_t)e0.x*32 + lane]);
        uint2 r1 = __ldg(&xh[(size_t)e1.x*32 + lane]);
        uint2 r2 = __ldg(&xh[(size_t)e2.x*32 + lane]);
        uint2 r3 = __ldg(&xh[(size_t)e3.x*32 + lane]);
        float w0 = __int_as_float(e0.y), w1 = __int_as_float(e1.y);
        float w2 = __int_as_float(e2.y), w3 = __int_as_float(e3.y);
        float2 a0 = __half22float2(*(__half2*)&r0.x), b0 = __half22float2(*(__half2*)&r0.y);
        float2 a1 = __half22float2(*(__half2*)&r1.x), b1 = __half22float2(*(__half2*)&r1.y);
        float2 a2 = __half22float2(*(__half2*)&r2.x), b2 = __half22float2(*(__half2*)&r2.y);
        float2 a3 = __half22float2(*(__half2*)&r3.x), b3 = __half22float2(*(__half2*)&r3.y);
        acc.x += w0*a0.x + w1*a1.x + w2*a2.x + w3*a3.x;
        acc.y += w0*a0.y + w1*a1.y + w2*a2.y + w3*a3.y;
        acc.z += w0*b0.x + w1*b1.x + w2*b2.x + w3*b3.x;
        acc.w += w0*b0.y + w1*b1.y + w2*b2.y + w3*b3.y;
    }
    for (; j < end; j++){
        int2 e0 = __ldg(&g_edge[j]);
        float w0 = __int_as_float(e0.y);
        uint2 r0 = __ldg(&xh[(size_t)e0.x*32 + lane]);
        float2 a0 = __half22float2(*(__half2*)&r0.x);
        float2 b0 = __half22float2(*(__half2*)&r0.y);
        acc.x += w0*a0.x; acc.y += w0*a0.y; acc.z += w0*b0.x; acc.w += w0*b0.y;
    }
    int n = w / RR, r = w - n*RR;
    h_store4((size_t)n*KK + r*DD + lane*4, acc);
}

// ---------------- weight transpose -> fp16, ALL layers ---------------------
__global__ void k_prepW(const float* __restrict__ Wrel, const float* __restrict__ brel,
                        const float* __restrict__ Wloop, const float* __restrict__ bloop){
    int i = blockIdx.x*blockDim.x + threadIdx.x;
    if (i < NLAYERS*KK*DD){
        int layer = i / (KK*DD);
        int rem   = i - layer*(KK*DD);
        int n = rem >> 10, k = rem & 1023;
        float v = (k < 896)
            ? Wrel [(size_t)layer*896*128 + (size_t)k*128 + n]
            : Wloop[(size_t)layer*128*128 + (size_t)(k-896)*128 + n];
        g_Bf3[layer][rem] = __float2half_rn(v);
    }
    if (i < NLAYERS*DD){
        int layer = i / DD, c = i - layer*DD;
        g_bias3[layer][c] = brel[layer*DD + c] + bloop[layer*DD + c];
    }
}

// ---------------- pipelined mma.sync GEMM (fp16, 3-stage, 1 bar/chunk) -----
// C[128tile,128] = Af * Bf^T, fp32 accum. Stage = 32KB; 3 stages; 2 CTAs/SM.
// Safety: issue(kc+2) targets stage (kc+2)%3 == (kc-1)%3, whose compute
// finished before every warp reached this iteration's __syncthreads.
__global__ void __launch_bounds__(256, 2) k_gemm_mma(float* __restrict__ xout,
                                                     int writeAux, int layer){
    extern __shared__ char dsm[];
    uint32_t sbase = smem_u32(dsm);

    int tid  = threadIdx.x;
    int wid  = tid >> 5;
    int lane = tid & 31;
    int wm   = wid & 3;      // 4 warps along M
    int wn   = wid >> 2;     // 2 warps along N
    int m0   = blockIdx.x * 128;

    const char* srcs[2] = {
        (const char*)g_Af + (size_t)m0*2048,
        (const char*)g_Bf3[layer] };

    int l_row[4], l_seg[4];
    #pragma unroll
    for (int i = 0; i < 4; i++){
        int idx = tid + i*256;
        l_row[i] = idx >> 3;
        l_seg[i] = (idx & 7) * 16;
    }

    uint32_t a_rowb = (uint32_t)(((lane & 7) + ((lane >> 3) & 1) * 8 + wm * 32) * 128);
    uint32_t a_kb   = ((lane >> 4) & 1) * 16;
    uint32_t b_rowb = (uint32_t)(((lane & 7) + ((lane >> 4) & 1) * 8 + wn * 64) * 128);
    uint32_t b_kb   = ((lane >> 3) & 1) * 16;

    float acc[2][8][4];
    #pragma unroll
    for (int mt = 0; mt < 2; mt++)
        #pragma unroll
        for (int nt = 0; nt < 8; nt++)
            #pragma unroll
            for (int q = 0; q < 4; q++) acc[mt][nt][q] = 0.f;

    auto issue = [&](int kc){
        size_t kbyte = (size_t)kc * 128;
        uint32_t sb = sbase + (uint32_t)(kc % NSTAGE)*STAGE_BYTES;
        #pragma unroll
        for (int t2 = 0; t2 < 2; t2++){
            #pragma unroll
            for (int i = 0; i < 4; i++){
                const char* src = srcs[t2] + (size_t)l_row[i]*2048 + kbyte + l_seg[i];
                uint32_t dst = sb + t2*16384 + SMEM_SWIZZLE_128B(l_row[i]*128 + l_seg[i]);
                CP_ASYNC16(dst, src);
            }
        }
    };

    issue(0); CP_COMMIT();
    issue(1); CP_COMMIT();

    for (int kc = 0; kc < NCHUNK; kc++){
        if (kc + 1 < NCHUNK) { CP_WAIT1(); } else { CP_WAIT0(); }
        __syncthreads();
        if (kc + 2 < NCHUNK){
            issue(kc + 2);
            CP_COMMIT();
        }

        uint32_t sb  = sbase + (uint32_t)(kc % NSTAGE)*STAGE_BYTES;
        uint32_t sAF = sb, sBF = sb + 16384;

        #pragma unroll
        for (int ks = 0; ks < 4; ks++){
            uint32_t koff = ks * 32;
            uint32_t a_off = SMEM_SWIZZLE_128B(a_rowb + a_kb + koff);
            uint32_t b_off = SMEM_SWIZZLE_128B(b_rowb + b_kb + koff);
            uint32_t af[2][4];
            #pragma unroll
            for (int mt = 0; mt < 2; mt++)
                ldsm4(af[mt], sAF + a_off + mt*2048);
            #pragma unroll
            for (int np = 0; np < 4; np++){
                uint32_t bf[4];
                ldsm4(bf, sBF + b_off + np*2048);
                #pragma unroll
                for (int half = 0; half < 2; half++){
                    int nt = np*2 + half;
                    #pragma unroll
                    for (int mt = 0; mt < 2; mt++)
                        mma16816(acc[mt][nt], af[mt], bf + half*2);
                }
            }
        }
    }

    // epilogue: bias + relu
    const float* bias = g_bias3[layer];
    int qrow = lane >> 2;            // 0..7
    int qcol = (lane & 3) * 2;       // 0,2,4,6
    #pragma unroll
    for (int mt = 0; mt < 2; mt++){
        #pragma unroll
        for (int nt = 0; nt < 8; nt++){
            int col  = wn*64 + nt*8 + qcol;
            float2 bb = *(const float2*)&bias[col];
            int r0 = m0 + wm*32 + mt*16 + qrow;
            int r1 = r0 + 8;
            float v00 = fmaxf(acc[mt][nt][0] + bb.x, 0.f);
            float v01 = fmaxf(acc[mt][nt][1] + bb.y, 0.f);
            float v10 = fmaxf(acc[mt][nt][2] + bb.x, 0.f);
            float v11 = fmaxf(acc[mt][nt][3] + bb.y, 0.f);
            if (writeAux){
                if (r0 < NN){
                    __half2 h = __floats2half2_rn(v00, v01);
                    *(__half2*)&g_xh[(size_t)r0*DD + col] = h;
                    *(__half2*)&g_Af[(size_t)r0*KK + 896 + col] = h;
                }
                if (r1 < NN){
                    __half2 h = __floats2half2_rn(v10, v11);
                    *(__half2*)&g_xh[(size_t)r1*DD + col] = h;
                    *(__half2*)&g_Af[(size_t)r1*KK + 896 + col] = h;
                }
            } else {
                if (r0 < NN) *(float2*)&xout[(size_t)r0*DD + col] = make_float2(v00, v01);
                if (r1 < NN) *(float2*)&xout[(size_t)r1*DD + col] = make_float2(v10, v11);
            }
        }
    }
}

// ---------------- graph pooling --------------------------------------------
__device__ __forceinline__ int lowerb(const int* __restrict__ a, int n, int key){
    int lo = 0, hi = n;
    while (lo < hi){
        int mid = (lo + hi) >> 1;
        if (a[mid] < key) lo = mid + 1; else hi = mid;
    }
    return lo;
}
__global__ void k_gsum(const int* __restrict__ n2g, const float* __restrict__ x,
                       float* __restrict__ out){
    int g = blockIdx.x / GSPLIT, c = blockIdx.x % GSPLIT, t = threadIdx.x;
    int lo = lowerb(n2g, NN, g);
    int hi = lowerb(n2g, NN, g+1);
    int len = hi - lo;
    int per = (len + GSPLIT - 1) / GSPLIT;
    int s = lo + c*per;
    int e = min(s + per, hi);
    float acc = 0.f;
    for (int n = s; n < e; n++) acc += x[(size_t)n*DD + t];
    if (e > s) atomicAdd(&out[g*DD + t], acc);
}

// ---------------- launcher --------------------------------------------------
extern "C" void kernel_launch(void* const* d_in, const int* in_sizes, int n_in,
                              void* d_out, int out_size){
    const int*   unit_type   = (const int*)  d_in[0];
    const int*   node_in     = (const int*)  d_in[1];
    const int*   node_out    = (const int*)  d_in[2];
    const int*   relation    = (const int*)  d_in[3];
    const float* edge_weight = (const float*)d_in[4];
    const int*   node2graph  = (const int*)  d_in[5];
    const float* emb         = (const float*)d_in[6];
    const float* W_rel       = (const float*)d_in[7];
    const float* b_rel       = (const float*)d_in[8];
    const float* W_loop      = (const float*)d_in[9];
    const float* b_loop      = (const float*)d_in[10];

    float* out   = (float*)d_out;
    float* x_out = out + GG*DD;

    // idempotent, capture-safe; no static guard (harness rule)
    cudaFuncSetAttribute(k_gemm_mma, cudaFuncAttributeMaxDynamicSharedMemorySize, GEMM_SMEM);

    int nb_ns = (NS + 1023) / 1024;  // 342

    k_embed_zero<<<(NN*32 + 255)/256, 256>>>(unit_type, (const float4*)emb);
    k_hist<<<(EE + 255)/256, 256>>>(node_out, relation);
    k_scan1<<<nb_ns, 1024>>>();
    k_scan23<<<nb_ns, 1024>>>(nb_ns);
    k_scatter<<<(EE + 255)/256, 256>>>(node_in, node_out, relation, edge_weight, out);

    for (int l = 0; l < NLAYERS; l++){
        k_agg<<<(NS*32 + 255)/256, 256>>>();
        if (l == 0)
            k_prepW<<<(NLAYERS*KK*DD + 255)/256, 256>>>(W_rel, b_rel, W_loop, b_loop);
        if (l < NLAYERS - 1)
            k_gemm_mma<<<MTILES, 256, GEMM_SMEM>>>(nullptr, 1, l);
        else
            k_gemm_mma<<<MTILES, 256, GEMM_SMEM>>>(x_out, 0, l);
    }

    k_gsum<<<GG*GSPLIT, 128>>>(node2graph, x_out, out);
}